// round 13
// baseline (speedup 1.0000x reference)
#include <cuda_runtime.h>

// ---------------------------------------------------------------------------
// BiSpikeNet forward, single persistent kernel. T=8, B=16, F=C*H*W=262144.
//
// R11 winner (53.7us) with ONE isolated change: the post-barrier broadcast
// chain is removed. After warp0 publishes its partial and arrives on the
// per-batch counter, EVERY thread spins on the counter and computes 1/denom
// itself from the 8 global partials (same sequential order -> bit-identical
// denominator). This deletes the second __syncthreads and the s_invd SMEM
// broadcast from every step; s_m is thread-private so no block sync is
// needed after the spin. Prefetch placement reverted to R11 (post-loop).
//
// 128 blocks (16 batches x 8 blocks/batch), 1024 threads. Membrane in SMEM
// (128 KiB), spike bits in registers (popc'd at the end). Barrier counters
// reset by a prologue kernel each launch (graph-replay safe).
// ---------------------------------------------------------------------------

namespace {
constexpr int T_STEPS        = 8;
constexpr int BATCH          = 16;
constexpr int FDIM           = 1 << 18;          // 262144
constexpr int BLKS_PER_BATCH = 8;
constexpr int NBLOCKS        = BATCH * BLKS_PER_BATCH;   // 128
constexpr int NTHREADS       = 1024;
constexpr int EPB            = FDIM / BLKS_PER_BATCH;    // 32768 elems/block
constexpr int KG             = EPB / (NTHREADS * 4);     // 8 float4 groups/thread
constexpr int NHEADS         = 4;
constexpr int HID            = 64;
constexpr int NBAR           = (T_STEPS + 1) * BATCH;    // 144 counters
}

__device__ unsigned int g_bar[NBAR];
__device__ float g_abs_part[T_STEPS][BATCH][BLKS_PER_BATCH];
__device__ unsigned int g_cnt_part[BATCH][BLKS_PER_BATCH][4];

__global__ void reset_kernel() {
    if (threadIdx.x < NBAR) g_bar[threadIdx.x] = 0u;
}

__device__ __forceinline__ void l2_prefetch(const void* p) {
    asm volatile("prefetch.global.L2 [%0];" :: "l"(p));
}

__global__ void __launch_bounds__(NTHREADS, 1) bispike_kernel(
    const float* __restrict__ x,
    const float* __restrict__ decay_p,
    const float* __restrict__ vth_p,
    const float* __restrict__ W1,
    const float* __restrict__ b1,
    const float* __restrict__ W2,
    const float* __restrict__ b2,
    const float* __restrict__ att_w,
    float* __restrict__ out)
{
    extern __shared__ float s_m[];               // EPB floats: membrane state
    __shared__ float s_red[32];
    __shared__ unsigned int s_redc[32];
    __shared__ float s_h[NHEADS * HID];
    __shared__ float s_maps[32];
    __shared__ float s_aw[T_STEPS];

    const int tid  = threadIdx.x;
    const int lane = tid & 31;
    const int warp = tid >> 5;
    const int b    = blockIdx.x >> 3;            // batch
    const int blk  = blockIdx.x & 7;             // slice within batch
    const int f0   = blk * EPB;

    const float d   = 1.0f / (1.0f + expf(-decay_p[0]));
    const float vth = vth_p[0];

    unsigned int bits4[KG];                      // 4 elements x 8 step-bits per word
#pragma unroll
    for (int k = 0; k < KG; k++) bits4[k] = 0u;

    float4* s_m4 = reinterpret_cast<float4*>(s_m);
    float inv_prev = 0.0f;

    const float* xbase = x + (size_t)b * FDIM + f0;

    // ---------------- temporal LIF loop ----------------
    for (int t = 0; t < T_STEPS; t++) {
        const float4* xp = reinterpret_cast<const float4*>(
            xbase + (size_t)t * BATCH * FDIM);
        float sa0 = 0.0f, sa1 = 0.0f, sa2 = 0.0f, sa3 = 0.0f;
#pragma unroll
        for (int k = 0; k < KG; k++) {
            const int idx4 = k * NTHREADS + tid;
            float4 xv = xp[idx4];
            float xa[4] = {xv.x, xv.y, xv.z, xv.w};
            float ma[4];
            if (t == 0) {
#pragma unroll
                for (int j = 0; j < 4; j++) ma[j] = xa[j];
            } else {
                float4 mo = s_m4[idx4];
                float moa[4] = {mo.x, mo.y, mo.z, mo.w};
#pragma unroll
                for (int j = 0; j < 4; j++) {
                    float mn = moa[j] * inv_prev;   // normalized m_{t-1}
                    bool  sp = (mn >= vth);
                    float sf = sp ? 1.0f : 0.0f;
                    if (sp) bits4[k] |= (1u << (8 * j + (t - 1)));
                    ma[j] = d * (mn - vth * sf) + xa[j];
                }
            }
            s_m4[idx4] = make_float4(ma[0], ma[1], ma[2], ma[3]);
            sa0 += fabsf(ma[0]); sa1 += fabsf(ma[1]);
            sa2 += fabsf(ma[2]); sa3 += fabsf(ma[3]);
        }
        float sum_abs = (sa0 + sa1) + (sa2 + sa3);

        // L2 prefetch of x[t+1] (R11 placement: after the loop, pre-barrier).
        // One prefetch per 128B line: lanes 0,8,16,24 cover the warp's span.
        if (t + 1 < T_STEPS && (lane & 7) == 0) {
            const float4* xn = reinterpret_cast<const float4*>(
                xbase + (size_t)(t + 1) * BATCH * FDIM);
#pragma unroll
            for (int k = 0; k < KG; k++)
                l2_prefetch(&xn[k * NTHREADS + tid]);
        }

        // deterministic block reduction (|m| sum only)
#pragma unroll
        for (int off = 16; off > 0; off >>= 1)
            sum_abs += __shfl_xor_sync(0xffffffffu, sum_abs, off);
        if (lane == 0) s_red[warp] = sum_abs;
        __syncthreads();
        if (warp == 0) {
            float v = s_red[lane];
#pragma unroll
            for (int off = 16; off > 0; off >>= 1)
                v += __shfl_xor_sync(0xffffffffu, v, off);
            if (lane == 0) {
                *(volatile float*)&g_abs_part[t][b][blk] = v;
                __threadfence();
                atomicAdd(&g_bar[t * BATCH + b], 1u);
            }
        }
        // ALL threads spin on the counter, then compute 1/denom themselves
        // (same sequential 8-partial order as R2/R11 -> bit-identical).
        // s_m is thread-private, so no __syncthreads is needed here; s_red
        // reuse is safe because warp0 read it BEFORE arriving on the counter.
        {
            volatile unsigned int* ctr = &g_bar[t * BATCH + b];
            while (*ctr < (unsigned)BLKS_PER_BATCH) { }
            volatile float* pp = &g_abs_part[t][b][0];
            float tot = 0.0f;
#pragma unroll
            for (int i = 0; i < BLKS_PER_BATCH; i++) tot += pp[i];
            float denom = tot * (1.0f / (float)FDIM) + 1e-6f;
            inv_prev = 1.0f / denom;
        }
    }

    // ---------------- final step spikes (t = T-1) ----------------
    {
#pragma unroll
        for (int k = 0; k < KG; k++) {
            const int idx4 = k * NTHREADS + tid;
            float4 mo = s_m4[idx4];
            float moa[4] = {mo.x, mo.y, mo.z, mo.w};
#pragma unroll
            for (int j = 0; j < 4; j++) {
                if (moa[j] * inv_prev >= vth)
                    bits4[k] |= (1u << (8 * j + 7));
            }
        }
    }

    // ---------------- spike counts via popc (packed 2x16-bit) -------------
    {
        unsigned int packed[4];
#pragma unroll
        for (int q = 0; q < 4; q++) {
            unsigned int c_lo = 0, c_hi = 0;
            unsigned int m_lo = 0x01010101u << (2 * q);
            unsigned int m_hi = 0x01010101u << (2 * q + 1);
#pragma unroll
            for (int k = 0; k < KG; k++) {
                c_lo += __popc(bits4[k] & m_lo);
                c_hi += __popc(bits4[k] & m_hi);
            }
            packed[q] = c_lo | (c_hi << 16);     // block count <= 32768: fits
        }
#pragma unroll
        for (int q = 0; q < 4; q++) {
            unsigned int v = packed[q];
#pragma unroll
            for (int off = 16; off > 0; off >>= 1)
                v += __shfl_xor_sync(0xffffffffu, v, off);
            if (lane == 0) s_redc[warp] = v;
            __syncthreads();
            if (warp == 0) {
                unsigned int c = s_redc[lane];
#pragma unroll
                for (int off = 16; off > 0; off >>= 1)
                    c += __shfl_xor_sync(0xffffffffu, c, off);
                if (lane == 0)
                    *(volatile unsigned int*)&g_cnt_part[b][blk][q] = c;
            }
            __syncthreads();
        }
        if (warp == 0 && lane == 0) {
            __threadfence();
            atomicAdd(&g_bar[T_STEPS * BATCH + b], 1u);
        }
        volatile unsigned int* ctr = &g_bar[T_STEPS * BATCH + b];
        while (*ctr < (unsigned)BLKS_PER_BATCH) { }
    }

    // ---------------- tiny attention MLP (warp 0, per batch) ----------------
    if (warp == 0) {
        float summ[T_STEPS];
#pragma unroll
        for (int q = 0; q < 4; q++) {
            unsigned int lo = 0, hi = 0;
            if (lane < BLKS_PER_BATCH) {
                unsigned int v = *(volatile unsigned int*)&g_cnt_part[b][lane][q];
                lo = v & 0xffffu;                 // unpack BEFORE cross-block sum
                hi = v >> 16;
            }
#pragma unroll
            for (int off = 16; off > 0; off >>= 1) {   // uniform, full-warp
                lo += __shfl_xor_sync(0xffffffffu, lo, off);
                hi += __shfl_xor_sync(0xffffffffu, hi, off);
            }
            summ[2 * q]     = (float)lo * (1.0f / (float)FDIM);
            summ[2 * q + 1] = (float)hi * (1.0f / (float)FDIM);
        }
        // h[n,hd] = relu(sum_t summ[t]*W1[n,hd,t] + b1[n,hd]); 256 vals, 8/lane
#pragma unroll
        for (int r = 0; r < 8; r++) {
            int idx = r * 32 + lane;
            float acc = b1[idx];
#pragma unroll
            for (int t = 0; t < T_STEPS; t++)
                acc += summ[t] * W1[idx * T_STEPS + t];
            s_h[idx] = fmaxf(acc, 0.0f);
        }
        __syncwarp();
        // maps[n,t] = sum_hd h[n,hd]*W2[n,t,hd] + b2[n,t];  lane = n*8+t
        {
            float acc = b2[lane];
            const int hb = (lane >> 3) * HID;
            const float* w2p = W2 + lane * HID;
#pragma unroll
            for (int hd = 0; hd < HID; hd++)
                acc += s_h[hb + hd] * w2p[hd];
            s_maps[lane] = acc * att_w[lane >> 3];
        }
        __syncwarp();
        if (lane == 0) {
            float w[T_STEPS];
            float mx = -1e30f;
#pragma unroll
            for (int t = 0; t < T_STEPS; t++) {
                w[t] = s_maps[t] + s_maps[8 + t] + s_maps[16 + t] + s_maps[24 + t];
                mx = fmaxf(mx, w[t]);
            }
            float ssum = 0.0f;
#pragma unroll
            for (int t = 0; t < T_STEPS; t++) { w[t] = expf(w[t] - mx); ssum += w[t]; }
            float inv = 1.0f / ssum;
#pragma unroll
            for (int t = 0; t < T_STEPS; t++) s_aw[t] = w[t] * inv;
        }
    }
    __syncthreads();

    float aw[T_STEPS];
#pragma unroll
    for (int t = 0; t < T_STEPS; t++) aw[t] = s_aw[t];

    // ---------------- output: out[b,f] = sum_t aw[t] * spike(t,f) ----------
    float4* op = reinterpret_cast<float4*>(out + (size_t)b * FDIM + f0);
#pragma unroll
    for (int k = 0; k < KG; k++) {
        unsigned int bt = bits4[k];
        float o[4];
#pragma unroll
        for (int j = 0; j < 4; j++) {
            float v = 0.0f;
#pragma unroll
            for (int t = 0; t < T_STEPS; t++)
                v += ((bt >> (8 * j + t)) & 1u) ? aw[t] : 0.0f;
            o[j] = v;
        }
        op[k * NTHREADS + tid] = make_float4(o[0], o[1], o[2], o[3]);
    }
}

extern "C" void kernel_launch(void* const* d_in, const int* in_sizes, int n_in,
                              void* d_out, int out_size) {
    (void)in_sizes; (void)n_in; (void)out_size;
    cudaFuncSetAttribute(bispike_kernel,
                         cudaFuncAttributeMaxDynamicSharedMemorySize,
                         EPB * (int)sizeof(float));
    reset_kernel<<<1, 256>>>();
    bispike_kernel<<<NBLOCKS, NTHREADS, EPB * sizeof(float)>>>(
        (const float*)d_in[0],   // x
        (const float*)d_in[1],   // decay_param
        (const float*)d_in[2],   // v_th
        (const float*)d_in[3],   // W1
        (const float*)d_in[4],   // b1
        (const float*)d_in[5],   // W2
        (const float*)d_in[6],   // b2
        (const float*)d_in[7],   // att_w
        (float*)d_out);
}

// round 14
// speedup vs baseline: 2.0347x; 2.0347x over previous
#include <cuda_runtime.h>

// ---------------------------------------------------------------------------
// BiSpikeNet forward, single persistent kernel. T=8, B=16, F=C*H*W=262144.
//
// R11 winner (53.7us) with ONE isolated change: the membrane state lives in
// REGISTERS (float4 m[8] = 32 floats/thread) instead of a 128 KiB SMEM
// array. The membrane is thread-private, so the per-step SMEM round trip
// (8x LDS.128 + 8x STS.128 per thread) and the 29-cyc LDS latency in every
// element's chain disappear. Barrier, reduction, and all arithmetic are
// byte-identical to R11 -> output bit-identical.
//
// 128 blocks (16 batches x 8 blocks/batch), 1024 threads. Spike bits in
// registers (popc'd at the end). Per-batch software barrier: warp0 lane0
// publishes + spins (1 thread/block -- R13 showed block-wide spins melt L2),
// broadcasts 1/denom via SMEM + syncthreads. Counters reset each launch.
// ---------------------------------------------------------------------------

namespace {
constexpr int T_STEPS        = 8;
constexpr int BATCH          = 16;
constexpr int FDIM           = 1 << 18;          // 262144
constexpr int BLKS_PER_BATCH = 8;
constexpr int NBLOCKS        = BATCH * BLKS_PER_BATCH;   // 128
constexpr int NTHREADS       = 1024;
constexpr int EPB            = FDIM / BLKS_PER_BATCH;    // 32768 elems/block
constexpr int KG             = EPB / (NTHREADS * 4);     // 8 float4 groups/thread
constexpr int NHEADS         = 4;
constexpr int HID            = 64;
constexpr int NBAR           = (T_STEPS + 1) * BATCH;    // 144 counters
}

__device__ unsigned int g_bar[NBAR];
__device__ float g_abs_part[T_STEPS][BATCH][BLKS_PER_BATCH];
__device__ unsigned int g_cnt_part[BATCH][BLKS_PER_BATCH][4];

__global__ void reset_kernel() {
    if (threadIdx.x < NBAR) g_bar[threadIdx.x] = 0u;
}

__device__ __forceinline__ void l2_prefetch(const void* p) {
    asm volatile("prefetch.global.L2 [%0];" :: "l"(p));
}

__global__ void __launch_bounds__(NTHREADS, 1) bispike_kernel(
    const float* __restrict__ x,
    const float* __restrict__ decay_p,
    const float* __restrict__ vth_p,
    const float* __restrict__ W1,
    const float* __restrict__ b1,
    const float* __restrict__ W2,
    const float* __restrict__ b2,
    const float* __restrict__ att_w,
    float* __restrict__ out)
{
    __shared__ float s_red[32];
    __shared__ unsigned int s_redc[32];
    __shared__ float s_h[NHEADS * HID];
    __shared__ float s_maps[32];
    __shared__ float s_aw[T_STEPS];
    __shared__ float s_invd;

    const int tid  = threadIdx.x;
    const int lane = tid & 31;
    const int warp = tid >> 5;
    const int b    = blockIdx.x >> 3;            // batch
    const int blk  = blockIdx.x & 7;             // slice within batch
    const int f0   = blk * EPB;

    const float d   = 1.0f / (1.0f + expf(-decay_p[0]));
    const float vth = vth_p[0];

    unsigned int bits4[KG];                      // 4 elements x 8 step-bits per word
#pragma unroll
    for (int k = 0; k < KG; k++) bits4[k] = 0u;

    float4 m[KG];                                // membrane state: 32 floats in regs
    float inv_prev = 0.0f;

    const float* xbase = x + (size_t)b * FDIM + f0;

    // ---------------- temporal LIF loop ----------------
    for (int t = 0; t < T_STEPS; t++) {
        const float4* xp = reinterpret_cast<const float4*>(
            xbase + (size_t)t * BATCH * FDIM);
        float sa0 = 0.0f, sa1 = 0.0f, sa2 = 0.0f, sa3 = 0.0f;
#pragma unroll
        for (int k = 0; k < KG; k++) {
            const int idx4 = k * NTHREADS + tid;
            float4 xv = xp[idx4];
            float xa[4] = {xv.x, xv.y, xv.z, xv.w};
            float ma[4];
            if (t == 0) {
#pragma unroll
                for (int j = 0; j < 4; j++) ma[j] = xa[j];
            } else {
                float moa[4] = {m[k].x, m[k].y, m[k].z, m[k].w};
#pragma unroll
                for (int j = 0; j < 4; j++) {
                    float mn = moa[j] * inv_prev;   // normalized m_{t-1}
                    bool  sp = (mn >= vth);
                    float sf = sp ? 1.0f : 0.0f;
                    if (sp) bits4[k] |= (1u << (8 * j + (t - 1)));
                    ma[j] = d * (mn - vth * sf) + xa[j];
                }
            }
            m[k] = make_float4(ma[0], ma[1], ma[2], ma[3]);
            sa0 += fabsf(ma[0]); sa1 += fabsf(ma[1]);
            sa2 += fabsf(ma[2]); sa3 += fabsf(ma[3]);
        }
        float sum_abs = (sa0 + sa1) + (sa2 + sa3);

        // L2 prefetch of x[t+1] (post-loop, pre-barrier -- R11 placement).
        // One prefetch per 128B line: lanes 0,8,16,24 cover the warp's span.
        if (t + 1 < T_STEPS && (lane & 7) == 0) {
            const float4* xn = reinterpret_cast<const float4*>(
                xbase + (size_t)(t + 1) * BATCH * FDIM);
#pragma unroll
            for (int k = 0; k < KG; k++)
                l2_prefetch(&xn[k * NTHREADS + tid]);
        }

        // deterministic block reduction (|m| sum only)
#pragma unroll
        for (int off = 16; off > 0; off >>= 1)
            sum_abs += __shfl_xor_sync(0xffffffffu, sum_abs, off);
        if (lane == 0) s_red[warp] = sum_abs;
        __syncthreads();
        if (warp == 0) {
            float v = s_red[lane];
#pragma unroll
            for (int off = 16; off > 0; off >>= 1)
                v += __shfl_xor_sync(0xffffffffu, v, off);
            if (lane == 0) {
                *(volatile float*)&g_abs_part[t][b][blk] = v;
                __threadfence();
                unsigned int* bar = &g_bar[t * BATCH + b];
                atomicAdd(bar, 1u);
                volatile unsigned int* ctr = bar;
                while (*ctr < (unsigned)BLKS_PER_BATCH) { }
                // deterministic 8-partial sum for this batch (same as R2)
                volatile float* pp = &g_abs_part[t][b][0];
                float tot = 0.0f;
#pragma unroll
                for (int i = 0; i < BLKS_PER_BATCH; i++) tot += pp[i];
                float denom = tot * (1.0f / (float)FDIM) + 1e-6f;
                s_invd = 1.0f / denom;
            }
        }
        __syncthreads();
        inv_prev = s_invd;
    }

    // ---------------- final step spikes (t = T-1) ----------------
    {
#pragma unroll
        for (int k = 0; k < KG; k++) {
            float moa[4] = {m[k].x, m[k].y, m[k].z, m[k].w};
#pragma unroll
            for (int j = 0; j < 4; j++) {
                if (moa[j] * inv_prev >= vth)
                    bits4[k] |= (1u << (8 * j + 7));
            }
        }
    }

    // ---------------- spike counts via popc (packed 2x16-bit) -------------
    {
        unsigned int packed[4];
#pragma unroll
        for (int q = 0; q < 4; q++) {
            unsigned int c_lo = 0, c_hi = 0;
            unsigned int m_lo = 0x01010101u << (2 * q);
            unsigned int m_hi = 0x01010101u << (2 * q + 1);
#pragma unroll
            for (int k = 0; k < KG; k++) {
                c_lo += __popc(bits4[k] & m_lo);
                c_hi += __popc(bits4[k] & m_hi);
            }
            packed[q] = c_lo | (c_hi << 16);     // block count <= 32768: fits
        }
#pragma unroll
        for (int q = 0; q < 4; q++) {
            unsigned int v = packed[q];
#pragma unroll
            for (int off = 16; off > 0; off >>= 1)
                v += __shfl_xor_sync(0xffffffffu, v, off);
            if (lane == 0) s_redc[warp] = v;
            __syncthreads();
            if (warp == 0) {
                unsigned int c = s_redc[lane];
#pragma unroll
                for (int off = 16; off > 0; off >>= 1)
                    c += __shfl_xor_sync(0xffffffffu, c, off);
                if (lane == 0)
                    *(volatile unsigned int*)&g_cnt_part[b][blk][q] = c;
            }
            __syncthreads();
        }
        if (warp == 0 && lane == 0) {
            __threadfence();
            unsigned int* bar = &g_bar[T_STEPS * BATCH + b];
            atomicAdd(bar, 1u);
            volatile unsigned int* ctr = bar;
            while (*ctr < (unsigned)BLKS_PER_BATCH) { }
        }
        __syncthreads();
    }

    // ---------------- tiny attention MLP (warp 0, per batch) ----------------
    if (warp == 0) {
        float summ[T_STEPS];
#pragma unroll
        for (int q = 0; q < 4; q++) {
            unsigned int lo = 0, hi = 0;
            if (lane < BLKS_PER_BATCH) {
                unsigned int v = *(volatile unsigned int*)&g_cnt_part[b][lane][q];
                lo = v & 0xffffu;                 // unpack BEFORE cross-block sum
                hi = v >> 16;
            }
#pragma unroll
            for (int off = 16; off > 0; off >>= 1) {   // uniform, full-warp
                lo += __shfl_xor_sync(0xffffffffu, lo, off);
                hi += __shfl_xor_sync(0xffffffffu, hi, off);
            }
            summ[2 * q]     = (float)lo * (1.0f / (float)FDIM);
            summ[2 * q + 1] = (float)hi * (1.0f / (float)FDIM);
        }
        // h[n,hd] = relu(sum_t summ[t]*W1[n,hd,t] + b1[n,hd]); 256 vals, 8/lane
#pragma unroll
        for (int r = 0; r < 8; r++) {
            int idx = r * 32 + lane;
            float acc = b1[idx];
#pragma unroll
            for (int t = 0; t < T_STEPS; t++)
                acc += summ[t] * W1[idx * T_STEPS + t];
            s_h[idx] = fmaxf(acc, 0.0f);
        }
        __syncwarp();
        // maps[n,t] = sum_hd h[n,hd]*W2[n,t,hd] + b2[n,t];  lane = n*8+t
        {
            float acc = b2[lane];
            const int hb = (lane >> 3) * HID;
            const float* w2p = W2 + lane * HID;
#pragma unroll
            for (int hd = 0; hd < HID; hd++)
                acc += s_h[hb + hd] * w2p[hd];
            s_maps[lane] = acc * att_w[lane >> 3];
        }
        __syncwarp();
        if (lane == 0) {
            float w[T_STEPS];
            float mx = -1e30f;
#pragma unroll
            for (int t = 0; t < T_STEPS; t++) {
                w[t] = s_maps[t] + s_maps[8 + t] + s_maps[16 + t] + s_maps[24 + t];
                mx = fmaxf(mx, w[t]);
            }
            float ssum = 0.0f;
#pragma unroll
            for (int t = 0; t < T_STEPS; t++) { w[t] = expf(w[t] - mx); ssum += w[t]; }
            float inv = 1.0f / ssum;
#pragma unroll
            for (int t = 0; t < T_STEPS; t++) s_aw[t] = w[t] * inv;
        }
    }
    __syncthreads();

    float aw[T_STEPS];
#pragma unroll
    for (int t = 0; t < T_STEPS; t++) aw[t] = s_aw[t];

    // ---------------- output: out[b,f] = sum_t aw[t] * spike(t,f) ----------
    float4* op = reinterpret_cast<float4*>(out + (size_t)b * FDIM + f0);
#pragma unroll
    for (int k = 0; k < KG; k++) {
        unsigned int bt = bits4[k];
        float o[4];
#pragma unroll
        for (int j = 0; j < 4; j++) {
            float v = 0.0f;
#pragma unroll
            for (int t = 0; t < T_STEPS; t++)
                v += ((bt >> (8 * j + t)) & 1u) ? aw[t] : 0.0f;
            o[j] = v;
        }
        op[k * NTHREADS + tid] = make_float4(o[0], o[1], o[2], o[3]);
    }
}

extern "C" void kernel_launch(void* const* d_in, const int* in_sizes, int n_in,
                              void* d_out, int out_size) {
    (void)in_sizes; (void)n_in; (void)out_size;
    reset_kernel<<<1, 256>>>();
    bispike_kernel<<<NBLOCKS, NTHREADS>>>(
        (const float*)d_in[0],   // x
        (const float*)d_in[1],   // decay_param
        (const float*)d_in[2],   // v_th
        (const float*)d_in[3],   // W1
        (const float*)d_in[4],   // b1
        (const float*)d_in[5],   // W2
        (const float*)d_in[6],   // b2
        (const float*)d_in[7],   // att_w
        (float*)d_out);
}

// round 15
// speedup vs baseline: 2.4575x; 1.2078x over previous
#include <cuda_runtime.h>

// ---------------------------------------------------------------------------
// BiSpikeNet forward, single persistent kernel. T=8, B=16, F=C*H*W=262144.
//
// R11 winner (53.7us) with two phase-disjoint cleanups:
//  (1) L2-prefetch of the MLP weights (W1,b1,W2,b2,att_w ~17KB) at kernel
//      start, so the tail's warp-0 MLP hits L2 instead of cold DRAM.
//  (2) t=0 peeled out of the temporal loop -> branch-free 7-step loop body.
// All arithmetic, ordering, barrier structure identical to R11 -> output
// bit-identical (rel_err 5.802389e-08).
//
// 128 blocks (16 batches x 8 blocks/batch), 1024 threads. Membrane in SMEM
// (128 KiB), spike bits in registers (popc'd at the end). Per-batch software
// barrier: warp0 lane0 publishes + spins (1 thread/block), broadcasts
// 1/denom via SMEM + syncthreads. Counters reset each launch.
// ---------------------------------------------------------------------------

namespace {
constexpr int T_STEPS        = 8;
constexpr int BATCH          = 16;
constexpr int FDIM           = 1 << 18;          // 262144
constexpr int BLKS_PER_BATCH = 8;
constexpr int NBLOCKS        = BATCH * BLKS_PER_BATCH;   // 128
constexpr int NTHREADS       = 1024;
constexpr int EPB            = FDIM / BLKS_PER_BATCH;    // 32768 elems/block
constexpr int KG             = EPB / (NTHREADS * 4);     // 8 float4 groups/thread
constexpr int NHEADS         = 4;
constexpr int HID            = 64;
constexpr int NBAR           = (T_STEPS + 1) * BATCH;    // 144 counters
constexpr int W1_ELEMS       = NHEADS * HID * T_STEPS;   // 2048
constexpr int W2_ELEMS       = NHEADS * T_STEPS * HID;   // 2048
}

__device__ unsigned int g_bar[NBAR];
__device__ float g_abs_part[T_STEPS][BATCH][BLKS_PER_BATCH];
__device__ unsigned int g_cnt_part[BATCH][BLKS_PER_BATCH][4];

__global__ void reset_kernel() {
    if (threadIdx.x < NBAR) g_bar[threadIdx.x] = 0u;
}

__device__ __forceinline__ void l2_prefetch(const void* p) {
    asm volatile("prefetch.global.L2 [%0];" :: "l"(p));
}

__global__ void __launch_bounds__(NTHREADS, 1) bispike_kernel(
    const float* __restrict__ x,
    const float* __restrict__ decay_p,
    const float* __restrict__ vth_p,
    const float* __restrict__ W1,
    const float* __restrict__ b1,
    const float* __restrict__ W2,
    const float* __restrict__ b2,
    const float* __restrict__ att_w,
    float* __restrict__ out)
{
    extern __shared__ float s_m[];               // EPB floats: membrane state
    __shared__ float s_red[32];
    __shared__ unsigned int s_redc[32];
    __shared__ float s_h[NHEADS * HID];
    __shared__ float s_maps[32];
    __shared__ float s_aw[T_STEPS];
    __shared__ float s_invd;

    const int tid  = threadIdx.x;
    const int lane = tid & 31;
    const int warp = tid >> 5;
    const int b    = blockIdx.x >> 3;            // batch
    const int blk  = blockIdx.x & 7;             // slice within batch
    const int f0   = blk * EPB;

    const float d   = 1.0f / (1.0f + expf(-decay_p[0]));
    const float vth = vth_p[0];

    // (1) prefetch the MLP weights into L2 once, at kernel start (warp 1,
    //     one prefetch per 128B line; hidden under t=0's DRAM phase)
    if (warp == 1) {
        for (int i = lane * 32; i < W1_ELEMS; i += 32 * 32) l2_prefetch(W1 + i);
        for (int i = lane * 32; i < W2_ELEMS; i += 32 * 32) l2_prefetch(W2 + i);
        if (lane < 8) l2_prefetch(b1 + lane * 32);
        if (lane == 8) l2_prefetch(b2);
        if (lane == 9) l2_prefetch(att_w);
    }

    unsigned int bits4[KG];                      // 4 elements x 8 step-bits per word
#pragma unroll
    for (int k = 0; k < KG; k++) bits4[k] = 0u;

    float4* s_m4 = reinterpret_cast<float4*>(s_m);
    float inv_prev = 0.0f;

    const float* xbase = x + (size_t)b * FDIM + f0;

    // ---------------- t = 0 (peeled): m = x ----------------
    {
        const float4* xp = reinterpret_cast<const float4*>(xbase);
        float sa0 = 0.0f, sa1 = 0.0f, sa2 = 0.0f, sa3 = 0.0f;
#pragma unroll
        for (int k = 0; k < KG; k++) {
            const int idx4 = k * NTHREADS + tid;
            float4 xv = xp[idx4];
            s_m4[idx4] = xv;
            sa0 += fabsf(xv.x); sa1 += fabsf(xv.y);
            sa2 += fabsf(xv.z); sa3 += fabsf(xv.w);
        }
        float sum_abs = (sa0 + sa1) + (sa2 + sa3);

        if ((lane & 7) == 0) {                   // prefetch x[1]
            const float4* xn = reinterpret_cast<const float4*>(
                xbase + (size_t)1 * BATCH * FDIM);
#pragma unroll
            for (int k = 0; k < KG; k++)
                l2_prefetch(&xn[k * NTHREADS + tid]);
        }

#pragma unroll
        for (int off = 16; off > 0; off >>= 1)
            sum_abs += __shfl_xor_sync(0xffffffffu, sum_abs, off);
        if (lane == 0) s_red[warp] = sum_abs;
        __syncthreads();
        if (warp == 0) {
            float v = s_red[lane];
#pragma unroll
            for (int off = 16; off > 0; off >>= 1)
                v += __shfl_xor_sync(0xffffffffu, v, off);
            if (lane == 0) {
                *(volatile float*)&g_abs_part[0][b][blk] = v;
                __threadfence();
                unsigned int* bar = &g_bar[0 * BATCH + b];
                atomicAdd(bar, 1u);
                volatile unsigned int* ctr = bar;
                while (*ctr < (unsigned)BLKS_PER_BATCH) { }
                volatile float* pp = &g_abs_part[0][b][0];
                float tot = 0.0f;
#pragma unroll
                for (int i = 0; i < BLKS_PER_BATCH; i++) tot += pp[i];
                float denom = tot * (1.0f / (float)FDIM) + 1e-6f;
                s_invd = 1.0f / denom;
            }
        }
        __syncthreads();
        inv_prev = s_invd;
    }

    // ---------------- t = 1..7 (branch-free body) ----------------
    for (int t = 1; t < T_STEPS; t++) {
        const float4* xp = reinterpret_cast<const float4*>(
            xbase + (size_t)t * BATCH * FDIM);
        float sa0 = 0.0f, sa1 = 0.0f, sa2 = 0.0f, sa3 = 0.0f;
#pragma unroll
        for (int k = 0; k < KG; k++) {
            const int idx4 = k * NTHREADS + tid;
            float4 xv = xp[idx4];
            float xa[4] = {xv.x, xv.y, xv.z, xv.w};
            float4 mo = s_m4[idx4];
            float moa[4] = {mo.x, mo.y, mo.z, mo.w};
            float ma[4];
#pragma unroll
            for (int j = 0; j < 4; j++) {
                float mn = moa[j] * inv_prev;    // normalized m_{t-1}
                bool  sp = (mn >= vth);
                float sf = sp ? 1.0f : 0.0f;
                if (sp) bits4[k] |= (1u << (8 * j + (t - 1)));
                ma[j] = d * (mn - vth * sf) + xa[j];
            }
            s_m4[idx4] = make_float4(ma[0], ma[1], ma[2], ma[3]);
            sa0 += fabsf(ma[0]); sa1 += fabsf(ma[1]);
            sa2 += fabsf(ma[2]); sa3 += fabsf(ma[3]);
        }
        float sum_abs = (sa0 + sa1) + (sa2 + sa3);

        // L2 prefetch of x[t+1] (post-loop, pre-barrier).
        if (t + 1 < T_STEPS && (lane & 7) == 0) {
            const float4* xn = reinterpret_cast<const float4*>(
                xbase + (size_t)(t + 1) * BATCH * FDIM);
#pragma unroll
            for (int k = 0; k < KG; k++)
                l2_prefetch(&xn[k * NTHREADS + tid]);
        }

#pragma unroll
        for (int off = 16; off > 0; off >>= 1)
            sum_abs += __shfl_xor_sync(0xffffffffu, sum_abs, off);
        if (lane == 0) s_red[warp] = sum_abs;
        __syncthreads();
        if (warp == 0) {
            float v = s_red[lane];
#pragma unroll
            for (int off = 16; off > 0; off >>= 1)
                v += __shfl_xor_sync(0xffffffffu, v, off);
            if (lane == 0) {
                *(volatile float*)&g_abs_part[t][b][blk] = v;
                __threadfence();
                unsigned int* bar = &g_bar[t * BATCH + b];
                atomicAdd(bar, 1u);
                volatile unsigned int* ctr = bar;
                while (*ctr < (unsigned)BLKS_PER_BATCH) { }
                volatile float* pp = &g_abs_part[t][b][0];
                float tot = 0.0f;
#pragma unroll
                for (int i = 0; i < BLKS_PER_BATCH; i++) tot += pp[i];
                float denom = tot * (1.0f / (float)FDIM) + 1e-6f;
                s_invd = 1.0f / denom;
            }
        }
        __syncthreads();
        inv_prev = s_invd;
    }

    // ---------------- final step spikes (t = T-1) ----------------
    {
#pragma unroll
        for (int k = 0; k < KG; k++) {
            const int idx4 = k * NTHREADS + tid;
            float4 mo = s_m4[idx4];
            float moa[4] = {mo.x, mo.y, mo.z, mo.w};
#pragma unroll
            for (int j = 0; j < 4; j++) {
                if (moa[j] * inv_prev >= vth)
                    bits4[k] |= (1u << (8 * j + 7));
            }
        }
    }

    // ---------------- spike counts via popc (packed 2x16-bit) -------------
    {
        unsigned int packed[4];
#pragma unroll
        for (int q = 0; q < 4; q++) {
            unsigned int c_lo = 0, c_hi = 0;
            unsigned int m_lo = 0x01010101u << (2 * q);
            unsigned int m_hi = 0x01010101u << (2 * q + 1);
#pragma unroll
            for (int k = 0; k < KG; k++) {
                c_lo += __popc(bits4[k] & m_lo);
                c_hi += __popc(bits4[k] & m_hi);
            }
            packed[q] = c_lo | (c_hi << 16);     // block count <= 32768: fits
        }
#pragma unroll
        for (int q = 0; q < 4; q++) {
            unsigned int v = packed[q];
#pragma unroll
            for (int off = 16; off > 0; off >>= 1)
                v += __shfl_xor_sync(0xffffffffu, v, off);
            if (lane == 0) s_redc[warp] = v;
            __syncthreads();
            if (warp == 0) {
                unsigned int c = s_redc[lane];
#pragma unroll
                for (int off = 16; off > 0; off >>= 1)
                    c += __shfl_xor_sync(0xffffffffu, c, off);
                if (lane == 0)
                    *(volatile unsigned int*)&g_cnt_part[b][blk][q] = c;
            }
            __syncthreads();
        }
        if (warp == 0 && lane == 0) {
            __threadfence();
            unsigned int* bar = &g_bar[T_STEPS * BATCH + b];
            atomicAdd(bar, 1u);
            volatile unsigned int* ctr = bar;
            while (*ctr < (unsigned)BLKS_PER_BATCH) { }
        }
        __syncthreads();
    }

    // ---------------- tiny attention MLP (warp 0, per batch) ----------------
    if (warp == 0) {
        float summ[T_STEPS];
#pragma unroll
        for (int q = 0; q < 4; q++) {
            unsigned int lo = 0, hi = 0;
            if (lane < BLKS_PER_BATCH) {
                unsigned int v = *(volatile unsigned int*)&g_cnt_part[b][lane][q];
                lo = v & 0xffffu;                 // unpack BEFORE cross-block sum
                hi = v >> 16;
            }
#pragma unroll
            for (int off = 16; off > 0; off >>= 1) {   // uniform, full-warp
                lo += __shfl_xor_sync(0xffffffffu, lo, off);
                hi += __shfl_xor_sync(0xffffffffu, hi, off);
            }
            summ[2 * q]     = (float)lo * (1.0f / (float)FDIM);
            summ[2 * q + 1] = (float)hi * (1.0f / (float)FDIM);
        }
        // h[n,hd] = relu(sum_t summ[t]*W1[n,hd,t] + b1[n,hd]); 256 vals, 8/lane
#pragma unroll
        for (int r = 0; r < 8; r++) {
            int idx = r * 32 + lane;
            float acc = b1[idx];
#pragma unroll
            for (int t = 0; t < T_STEPS; t++)
                acc += summ[t] * W1[idx * T_STEPS + t];
            s_h[idx] = fmaxf(acc, 0.0f);
        }
        __syncwarp();
        // maps[n,t] = sum_hd h[n,hd]*W2[n,t,hd] + b2[n,t];  lane = n*8+t
        {
            float acc = b2[lane];
            const int hb = (lane >> 3) * HID;
            const float* w2p = W2 + lane * HID;
#pragma unroll
            for (int hd = 0; hd < HID; hd++)
                acc += s_h[hb + hd] * w2p[hd];
            s_maps[lane] = acc * att_w[lane >> 3];
        }
        __syncwarp();
        if (lane == 0) {
            float w[T_STEPS];
            float mx = -1e30f;
#pragma unroll
            for (int t = 0; t < T_STEPS; t++) {
                w[t] = s_maps[t] + s_maps[8 + t] + s_maps[16 + t] + s_maps[24 + t];
                mx = fmaxf(mx, w[t]);
            }
            float ssum = 0.0f;
#pragma unroll
            for (int t = 0; t < T_STEPS; t++) { w[t] = expf(w[t] - mx); ssum += w[t]; }
            float inv = 1.0f / ssum;
#pragma unroll
            for (int t = 0; t < T_STEPS; t++) s_aw[t] = w[t] * inv;
        }
    }
    __syncthreads();

    float aw[T_STEPS];
#pragma unroll
    for (int t = 0; t < T_STEPS; t++) aw[t] = s_aw[t];

    // ---------------- output: out[b,f] = sum_t aw[t] * spike(t,f) ----------
    float4* op = reinterpret_cast<float4*>(out + (size_t)b * FDIM + f0);
#pragma unroll
    for (int k = 0; k < KG; k++) {
        unsigned int bt = bits4[k];
        float o[4];
#pragma unroll
        for (int j = 0; j < 4; j++) {
            float v = 0.0f;
#pragma unroll
            for (int t = 0; t < T_STEPS; t++)
                v += ((bt >> (8 * j + t)) & 1u) ? aw[t] : 0.0f;
            o[j] = v;
        }
        op[k * NTHREADS + tid] = make_float4(o[0], o[1], o[2], o[3]);
    }
}

extern "C" void kernel_launch(void* const* d_in, const int* in_sizes, int n_in,
                              void* d_out, int out_size) {
    (void)in_sizes; (void)n_in; (void)out_size;
    cudaFuncSetAttribute(bispike_kernel,
                         cudaFuncAttributeMaxDynamicSharedMemorySize,
                         EPB * (int)sizeof(float));
    reset_kernel<<<1, 256>>>();
    bispike_kernel<<<NBLOCKS, NTHREADS, EPB * sizeof(float)>>>(
        (const float*)d_in[0],   // x
        (const float*)d_in[1],   // decay_param
        (const float*)d_in[2],   // v_th
        (const float*)d_in[3],   // W1
        (const float*)d_in[4],   // b1
        (const float*)d_in[5],   // W2
        (const float*)d_in[6],   // b2
        (const float*)d_in[7],   // att_w
        (float*)d_out);
}

// round 16
// speedup vs baseline: 2.5793x; 1.0496x over previous
#include <cuda_runtime.h>

// ---------------------------------------------------------------------------
// BiSpikeNet forward, single persistent kernel. T=8, B=16, F=C*H*W=262144.
//
// R11 winner (53.7us) with ONE isolated change: the barrier-release gather
// of the 8 per-block partials is two ld.volatile.global.v4.f32 (2 L2 round
// trips) instead of 8 serial dependent scalar volatile loads (~2000 cyc on
// the per-step critical path). The 8 values are summed in the SAME
// sequential order -> denominator and output bit-identical to R11.
//
// 128 blocks (16 batches x 8 blocks/batch), 1024 threads. Membrane in SMEM
// (128 KiB), spike bits in registers (popc'd at the end). Per-batch software
// barrier: warp0 lane0 publishes + spins (1 thread/block), broadcasts
// 1/denom via SMEM + syncthreads. Counters reset each launch.
// ---------------------------------------------------------------------------

namespace {
constexpr int T_STEPS        = 8;
constexpr int BATCH          = 16;
constexpr int FDIM           = 1 << 18;          // 262144
constexpr int BLKS_PER_BATCH = 8;
constexpr int NBLOCKS        = BATCH * BLKS_PER_BATCH;   // 128
constexpr int NTHREADS       = 1024;
constexpr int EPB            = FDIM / BLKS_PER_BATCH;    // 32768 elems/block
constexpr int KG             = EPB / (NTHREADS * 4);     // 8 float4 groups/thread
constexpr int NHEADS         = 4;
constexpr int HID            = 64;
constexpr int NBAR           = (T_STEPS + 1) * BATCH;    // 144 counters
}

__device__ unsigned int g_bar[NBAR];
__device__ __align__(32) float g_abs_part[T_STEPS][BATCH][BLKS_PER_BATCH];
__device__ unsigned int g_cnt_part[BATCH][BLKS_PER_BATCH][4];

__global__ void reset_kernel() {
    if (threadIdx.x < NBAR) g_bar[threadIdx.x] = 0u;
}

__device__ __forceinline__ void l2_prefetch(const void* p) {
    asm volatile("prefetch.global.L2 [%0];" :: "l"(p));
}

__device__ __forceinline__ float4 ldg_volatile_v4(const float* p) {
    float4 v;
    asm volatile("ld.volatile.global.v4.f32 {%0,%1,%2,%3}, [%4];"
                 : "=f"(v.x), "=f"(v.y), "=f"(v.z), "=f"(v.w) : "l"(p));
    return v;
}

__global__ void __launch_bounds__(NTHREADS, 1) bispike_kernel(
    const float* __restrict__ x,
    const float* __restrict__ decay_p,
    const float* __restrict__ vth_p,
    const float* __restrict__ W1,
    const float* __restrict__ b1,
    const float* __restrict__ W2,
    const float* __restrict__ b2,
    const float* __restrict__ att_w,
    float* __restrict__ out)
{
    extern __shared__ float s_m[];               // EPB floats: membrane state
    __shared__ float s_red[32];
    __shared__ unsigned int s_redc[32];
    __shared__ float s_h[NHEADS * HID];
    __shared__ float s_maps[32];
    __shared__ float s_aw[T_STEPS];
    __shared__ float s_invd;

    const int tid  = threadIdx.x;
    const int lane = tid & 31;
    const int warp = tid >> 5;
    const int b    = blockIdx.x >> 3;            // batch
    const int blk  = blockIdx.x & 7;             // slice within batch
    const int f0   = blk * EPB;

    const float d   = 1.0f / (1.0f + expf(-decay_p[0]));
    const float vth = vth_p[0];

    unsigned int bits4[KG];                      // 4 elements x 8 step-bits per word
#pragma unroll
    for (int k = 0; k < KG; k++) bits4[k] = 0u;

    float4* s_m4 = reinterpret_cast<float4*>(s_m);
    float inv_prev = 0.0f;

    const float* xbase = x + (size_t)b * FDIM + f0;

    // ---------------- temporal LIF loop ----------------
    for (int t = 0; t < T_STEPS; t++) {
        const float4* xp = reinterpret_cast<const float4*>(
            xbase + (size_t)t * BATCH * FDIM);
        float sa0 = 0.0f, sa1 = 0.0f, sa2 = 0.0f, sa3 = 0.0f;
#pragma unroll
        for (int k = 0; k < KG; k++) {
            const int idx4 = k * NTHREADS + tid;
            float4 xv = xp[idx4];
            float xa[4] = {xv.x, xv.y, xv.z, xv.w};
            float ma[4];
            if (t == 0) {
#pragma unroll
                for (int j = 0; j < 4; j++) ma[j] = xa[j];
            } else {
                float4 mo = s_m4[idx4];
                float moa[4] = {mo.x, mo.y, mo.z, mo.w};
#pragma unroll
                for (int j = 0; j < 4; j++) {
                    float mn = moa[j] * inv_prev;   // normalized m_{t-1}
                    bool  sp = (mn >= vth);
                    float sf = sp ? 1.0f : 0.0f;
                    if (sp) bits4[k] |= (1u << (8 * j + (t - 1)));
                    ma[j] = d * (mn - vth * sf) + xa[j];
                }
            }
            s_m4[idx4] = make_float4(ma[0], ma[1], ma[2], ma[3]);
            sa0 += fabsf(ma[0]); sa1 += fabsf(ma[1]);
            sa2 += fabsf(ma[2]); sa3 += fabsf(ma[3]);
        }
        float sum_abs = (sa0 + sa1) + (sa2 + sa3);

        // L2 prefetch of x[t+1] while we reduce + wait at the barrier.
        // One prefetch per 128B line: lanes 0,8,16,24 cover the warp's span.
        if (t + 1 < T_STEPS && (lane & 7) == 0) {
            const float4* xn = reinterpret_cast<const float4*>(
                xbase + (size_t)(t + 1) * BATCH * FDIM);
#pragma unroll
            for (int k = 0; k < KG; k++)
                l2_prefetch(&xn[k * NTHREADS + tid]);
        }

        // deterministic block reduction (|m| sum only)
#pragma unroll
        for (int off = 16; off > 0; off >>= 1)
            sum_abs += __shfl_xor_sync(0xffffffffu, sum_abs, off);
        if (lane == 0) s_red[warp] = sum_abs;
        __syncthreads();
        if (warp == 0) {
            float v = s_red[lane];
#pragma unroll
            for (int off = 16; off > 0; off >>= 1)
                v += __shfl_xor_sync(0xffffffffu, v, off);
            if (lane == 0) {
                *(volatile float*)&g_abs_part[t][b][blk] = v;
                __threadfence();
                unsigned int* bar = &g_bar[t * BATCH + b];
                atomicAdd(bar, 1u);
                volatile unsigned int* ctr = bar;
                while (*ctr < (unsigned)BLKS_PER_BATCH) { }
                // gather the 8 partials as TWO v4 loads (2 round trips),
                // summed in the same sequential order -> bit-identical
                float4 p0 = ldg_volatile_v4(&g_abs_part[t][b][0]);
                float4 p1 = ldg_volatile_v4(&g_abs_part[t][b][4]);
                float tot = 0.0f;
                tot += p0.x; tot += p0.y; tot += p0.z; tot += p0.w;
                tot += p1.x; tot += p1.y; tot += p1.z; tot += p1.w;
                float denom = tot * (1.0f / (float)FDIM) + 1e-6f;
                s_invd = 1.0f / denom;
            }
        }
        __syncthreads();
        inv_prev = s_invd;
    }

    // ---------------- final step spikes (t = T-1) ----------------
    {
#pragma unroll
        for (int k = 0; k < KG; k++) {
            const int idx4 = k * NTHREADS + tid;
            float4 mo = s_m4[idx4];
            float moa[4] = {mo.x, mo.y, mo.z, mo.w};
#pragma unroll
            for (int j = 0; j < 4; j++) {
                if (moa[j] * inv_prev >= vth)
                    bits4[k] |= (1u << (8 * j + 7));
            }
        }
    }

    // ---------------- spike counts via popc (packed 2x16-bit) -------------
    {
        unsigned int packed[4];
#pragma unroll
        for (int q = 0; q < 4; q++) {
            unsigned int c_lo = 0, c_hi = 0;
            unsigned int m_lo = 0x01010101u << (2 * q);
            unsigned int m_hi = 0x01010101u << (2 * q + 1);
#pragma unroll
            for (int k = 0; k < KG; k++) {
                c_lo += __popc(bits4[k] & m_lo);
                c_hi += __popc(bits4[k] & m_hi);
            }
            packed[q] = c_lo | (c_hi << 16);     // block count <= 32768: fits
        }
#pragma unroll
        for (int q = 0; q < 4; q++) {
            unsigned int v = packed[q];
#pragma unroll
            for (int off = 16; off > 0; off >>= 1)
                v += __shfl_xor_sync(0xffffffffu, v, off);
            if (lane == 0) s_redc[warp] = v;
            __syncthreads();
            if (warp == 0) {
                unsigned int c = s_redc[lane];
#pragma unroll
                for (int off = 16; off > 0; off >>= 1)
                    c += __shfl_xor_sync(0xffffffffu, c, off);
                if (lane == 0)
                    *(volatile unsigned int*)&g_cnt_part[b][blk][q] = c;
            }
            __syncthreads();
        }
        if (warp == 0 && lane == 0) {
            __threadfence();
            unsigned int* bar = &g_bar[T_STEPS * BATCH + b];
            atomicAdd(bar, 1u);
            volatile unsigned int* ctr = bar;
            while (*ctr < (unsigned)BLKS_PER_BATCH) { }
        }
        __syncthreads();
    }

    // ---------------- tiny attention MLP (warp 0, per batch) ----------------
    if (warp == 0) {
        float summ[T_STEPS];
#pragma unroll
        for (int q = 0; q < 4; q++) {
            unsigned int lo = 0, hi = 0;
            if (lane < BLKS_PER_BATCH) {
                unsigned int v = *(volatile unsigned int*)&g_cnt_part[b][lane][q];
                lo = v & 0xffffu;                 // unpack BEFORE cross-block sum
                hi = v >> 16;
            }
#pragma unroll
            for (int off = 16; off > 0; off >>= 1) {   // uniform, full-warp
                lo += __shfl_xor_sync(0xffffffffu, lo, off);
                hi += __shfl_xor_sync(0xffffffffu, hi, off);
            }
            summ[2 * q]     = (float)lo * (1.0f / (float)FDIM);
            summ[2 * q + 1] = (float)hi * (1.0f / (float)FDIM);
        }
        // h[n,hd] = relu(sum_t summ[t]*W1[n,hd,t] + b1[n,hd]); 256 vals, 8/lane
#pragma unroll
        for (int r = 0; r < 8; r++) {
            int idx = r * 32 + lane;
            float acc = b1[idx];
#pragma unroll
            for (int t = 0; t < T_STEPS; t++)
                acc += summ[t] * W1[idx * T_STEPS + t];
            s_h[idx] = fmaxf(acc, 0.0f);
        }
        __syncwarp();
        // maps[n,t] = sum_hd h[n,hd]*W2[n,t,hd] + b2[n,t];  lane = n*8+t
        {
            float acc = b2[lane];
            const int hb = (lane >> 3) * HID;
            const float* w2p = W2 + lane * HID;
#pragma unroll
            for (int hd = 0; hd < HID; hd++)
                acc += s_h[hb + hd] * w2p[hd];
            s_maps[lane] = acc * att_w[lane >> 3];
        }
        __syncwarp();
        if (lane == 0) {
            float w[T_STEPS];
            float mx = -1e30f;
#pragma unroll
            for (int t = 0; t < T_STEPS; t++) {
                w[t] = s_maps[t] + s_maps[8 + t] + s_maps[16 + t] + s_maps[24 + t];
                mx = fmaxf(mx, w[t]);
            }
            float ssum = 0.0f;
#pragma unroll
            for (int t = 0; t < T_STEPS; t++) { w[t] = expf(w[t] - mx); ssum += w[t]; }
            float inv = 1.0f / ssum;
#pragma unroll
            for (int t = 0; t < T_STEPS; t++) s_aw[t] = w[t] * inv;
        }
    }
    __syncthreads();

    float aw[T_STEPS];
#pragma unroll
    for (int t = 0; t < T_STEPS; t++) aw[t] = s_aw[t];

    // ---------------- output: out[b,f] = sum_t aw[t] * spike(t,f) ----------
    float4* op = reinterpret_cast<float4*>(out + (size_t)b * FDIM + f0);
#pragma unroll
    for (int k = 0; k < KG; k++) {
        unsigned int bt = bits4[k];
        float o[4];
#pragma unroll
        for (int j = 0; j < 4; j++) {
            float v = 0.0f;
#pragma unroll
            for (int t = 0; t < T_STEPS; t++)
                v += ((bt >> (8 * j + t)) & 1u) ? aw[t] : 0.0f;
            o[j] = v;
        }
        op[k * NTHREADS + tid] = make_float4(o[0], o[1], o[2], o[3]);
    }
}

extern "C" void kernel_launch(void* const* d_in, const int* in_sizes, int n_in,
                              void* d_out, int out_size) {
    (void)in_sizes; (void)n_in; (void)out_size;
    cudaFuncSetAttribute(bispike_kernel,
                         cudaFuncAttributeMaxDynamicSharedMemorySize,
                         EPB * (int)sizeof(float));
    reset_kernel<<<1, 256>>>();
    bispike_kernel<<<NBLOCKS, NTHREADS, EPB * sizeof(float)>>>(
        (const float*)d_in[0],   // x
        (const float*)d_in[1],   // decay_param
        (const float*)d_in[2],   // v_th
        (const float*)d_in[3],   // W1
        (const float*)d_in[4],   // b1
        (const float*)d_in[5],   // W2
        (const float*)d_in[6],   // b2
        (const float*)d_in[7],   // att_w
        (float*)d_out);
}